// round 12
// baseline (speedup 1.0000x reference)
#include <cuda_runtime.h>
#include <cstdint>

// Problem constants
#define NN 512
#define KK 17
#define WW 48
#define HH 64
#define NK (NN * KK)                       // 8704
#define HMSZ (HH * WW)                     // 3072 floats
#define HMBYTES (HMSZ * 4)                 // 12288 bytes
#define TOTAL ((double)NN * KK * HH * WW)  // 26738688

#define GRID 148                           // <=1 block/SM (also on 152-SM GB300)
#define STAGES 16
#define CONS_WARPS 12
#define CONS_THREADS (CONS_WARPS * 32)     // 384 (768 quads -> 2 per thread)
#define NTHREADS (CONS_THREADS + 32)       // 416 (+1 producer warp)

// Stage layout: [data 12288][ex 192][ey 256][coef 4 + pad] = 12800 bytes
#define STAGE_BYTES (HMBYTES + 512)
#define OFF_EX (HMBYTES)
#define OFF_EY (HMBYTES + WW * 4)
#define OFF_CF (HMBYTES + WW * 4 + HH * 4)
#define SMEM_TOTAL (STAGES * STAGE_BYTES + STAGES * 16)   // 205056 <= 227KB

__device__ double g_acc;          // zero-init; reset by last block each run
__device__ unsigned int g_cnt;    // ditto

// ---- mbarrier / bulk-copy helpers ----
__device__ __forceinline__ uint32_t s2u(const void* p) {
    return (uint32_t)__cvta_generic_to_shared(p);
}
__device__ __forceinline__ void mbar_init(uint32_t a, uint32_t cnt) {
    asm volatile("mbarrier.init.shared.b64 [%0], %1;" :: "r"(a), "r"(cnt) : "memory");
}
__device__ __forceinline__ void mbar_arrive(uint32_t a) {
    asm volatile("mbarrier.arrive.shared.b64 _, [%0];" :: "r"(a) : "memory");
}
__device__ __forceinline__ void mbar_expect_tx(uint32_t a, uint32_t bytes) {
    asm volatile("mbarrier.arrive.expect_tx.shared.b64 _, [%0], %1;"
                 :: "r"(a), "r"(bytes) : "memory");
}
__device__ __forceinline__ void mbar_wait(uint32_t a, uint32_t parity) {
    asm volatile(
        "{\n\t.reg .pred P;\n\t"
        "W_%=:\n\t"
        "mbarrier.try_wait.parity.acquire.cta.shared::cta.b64 P, [%0], %1, 0x989680;\n\t"
        "@P bra.uni D_%=;\n\t"
        "bra.uni W_%=;\n\t"
        "D_%=:\n\t}"
        :: "r"(a), "r"(parity) : "memory");
}
__device__ __forceinline__ void bulk_g2s(uint32_t dst, const void* src,
                                         uint32_t bytes, uint32_t mbar) {
    asm volatile(
        "cp.async.bulk.shared::cta.global.mbarrier::complete_tx::bytes [%0], [%1], %2, [%3];"
        :: "r"(dst), "l"(src), "r"(bytes), "r"(mbar) : "memory");
}

extern __shared__ __align__(16) unsigned char smem[];

__global__ void __launch_bounds__(NTHREADS, 1) loss_kernel(
    const float* __restrict__ pred,      // [N,K,2]
    const float* __restrict__ sigma,     // [N,K,2]
    const float* __restrict__ teacher,   // [N,K,H,W]
    const float* __restrict__ twgt,      // [N,K,1]
    float* __restrict__ out)             // [1]
{
    const int tid  = threadIdx.x;
    const int wid  = tid >> 5;
    const int lane = tid & 31;
    const int bid  = blockIdx.x;

    const uint32_t sb   = s2u(smem);
    const uint32_t bars = sb + STAGES * STAGE_BYTES;  // full(s)=+s*16, empty(s)=+s*16+8

    if (tid == 0) {
        for (int s = 0; s < STAGES; s++) {
            mbar_init(bars + s * 16,     33);           // 1 expect_tx-arrive + 32 table arrives
            mbar_init(bars + s * 16 + 8, CONS_WARPS);   // consumer-warp leaders
        }
    }
    __syncthreads();

    float acc = 0.0f;

    if (wid == CONS_WARPS) {
        // ================= producer warp =================
        // Param pipeline, prefetch distance 2 (covers LDG latency with stage cadence).
        float mux0 = pred[bid * 2 + 0] * (float)WW;
        float muy0 = pred[bid * 2 + 1] * (float)HH;
        float sx0  = sigma[bid * 2 + 0];
        float sy0  = sigma[bid * 2 + 1];
        float tw0  = twgt[bid];
        const int nkB = bid + GRID;                     // always < NK
        float mux1 = pred[nkB * 2 + 0] * (float)WW;
        float muy1 = pred[nkB * 2 + 1] * (float)HH;
        float sx1  = sigma[nkB * 2 + 0];
        float sy1  = sigma[nkB * 2 + 1];
        float tw1  = twgt[nkB];

        int s = 0, ph = 1;                              // fresh empty barriers pass parity-1
        for (int nk = bid; nk < NK; nk += GRID) {
            const int nk2 = nk + 2 * GRID;
            float mux2 = 0.f, muy2 = 0.f, sx2 = 1.f, sy2 = 1.f, tw2 = 0.f;
            if (nk2 < NK) {
                mux2 = pred[nk2 * 2 + 0] * (float)WW;
                muy2 = pred[nk2 * 2 + 1] * (float)HH;
                sx2  = sigma[nk2 * 2 + 0];
                sy2  = sigma[nk2 * 2 + 1];
                tw2  = twgt[nk2];
            }

            mbar_wait(bars + s * 16 + 8, ph);           // stage free?
            __syncwarp();
            const uint32_t full = bars + s * 16;
            if (lane == 0) {
                mbar_expect_tx(full, HMBYTES);
                bulk_g2s(sb + s * STAGE_BYTES, teacher + (size_t)nk * HMSZ,
                         HMBYTES, full);
            }

            // Tables for nk (params loaded 2 stages ago) into this stage's slot.
            {
                float invx = 1.0f / (sx0 * sx0 + 1e-9f);
                float invy = 1.0f / (sy0 * sy0 + 1e-9f);
                float* exs = (float*)(smem + s * STAGE_BYTES + OFF_EX);
                float* eys = (float*)(smem + s * STAGE_BYTES + OFF_EY);
                float* cfs = (float*)(smem + s * STAGE_BYTES + OFF_CF);
                float d = (float)lane - mux0;
                exs[lane] = __expf(-0.5f * d * d * invx);
                if (lane < WW - 32) {
                    float d2 = (float)(lane + 32) - mux0;
                    exs[lane + 32] = __expf(-0.5f * d2 * d2 * invx);
                }
                float dy = (float)lane - muy0;
                eys[lane] = __expf(-0.5f * dy * dy * invy);
                float dy2 = (float)(lane + 32) - muy0;
                eys[lane + 32] = __expf(-0.5f * dy2 * dy2 * invy);
                if (lane == 0) {
                    float m = ((mux0 - 3.0f * sx0 < (float)WW) &&
                               (muy0 - 3.0f * sy0 < (float)HH) &&
                               (mux0 + 3.0f * sx0 + 1.0f >= 0.0f) &&
                               (muy0 + 3.0f * sy0 + 1.0f >= 0.0f)) ? 1.0f : 0.0f;
                    float t = tw0 * m;
                    cfs[0] = t * t;
                }
            }
            mbar_arrive(full);                          // release: tables visible

            mux0 = mux1; muy0 = muy1; sx0 = sx1; sy0 = sy1; tw0 = tw1;
            mux1 = mux2; muy1 = muy2; sx1 = sx2; sy1 = sy2; tw1 = tw2;
            if (++s == STAGES) { s = 0; ph ^= 1; }
        }
    } else {
        // ================= consumer warps =================
        const int q0 = tid;                 // quad 0..383
        const int q1 = tid + CONS_THREADS;  // quad 384..767
        const int h0 = q0 / 12, c0 = q0 % 12;
        const int h1 = q1 / 12, c1 = q1 % 12;

        int s = 0, ph = 0;
        for (int nk = bid; nk < NK; nk += GRID) {
            mbar_wait(bars + s * 16, ph);               // acquire: data + tables ready
            const char* stg = (const char*)smem + s * STAGE_BYTES;
            const float4* tp  = (const float4*)stg;
            const float4* ex4 = (const float4*)(stg + OFF_EX);
            const float*  eys = (const float*)(stg + OFF_EY);
            const float   cf  = *(const float*)(stg + OFF_CF);

            float4 t0 = tp[q0], t1 = tp[q1];
            float4 e0 = ex4[c0], e1 = ex4[c1];
            float  y0 = eys[h0], y1 = eys[h1];

            float d0 = e0.x * y0 - t0.x;
            float d1 = e0.y * y0 - t0.y;
            float d2 = e0.z * y0 - t0.z;
            float d3 = e0.w * y0 - t0.w;
            float ss = d0 * d0 + d1 * d1 + d2 * d2 + d3 * d3;
            d0 = e1.x * y1 - t1.x;
            d1 = e1.y * y1 - t1.y;
            d2 = e1.z * y1 - t1.z;
            d3 = e1.w * y1 - t1.w;
            ss += d0 * d0 + d1 * d1 + d2 * d2 + d3 * d3;
            acc += ss * cf;

            __syncwarp();                               // all lanes consumed stage
            if (lane == 0) mbar_arrive(bars + s * 16 + 8);
            if (++s == STAGES) { s = 0; ph ^= 1; }
        }
    }

    // ================= block reduce + finalize =================
    __shared__ float s_warp[CONS_WARPS + 1];
#pragma unroll
    for (int off = 16; off > 0; off >>= 1)
        acc += __shfl_down_sync(0xFFFFFFFFu, acc, off);
    if (lane == 0) s_warp[wid] = acc;
    __syncthreads();

    if (tid == 0) {
        float t = 0.f;
#pragma unroll
        for (int i = 0; i < CONS_WARPS + 1; i++) t += s_warp[i];
        atomicAdd(&g_acc, (double)t);
        __threadfence();
        unsigned int ticket = atomicAdd(&g_cnt, 1u);
        if (ticket == GRID - 1) {
            double total = atomicAdd(&g_acc, 0.0);   // coherent read of all adds
            out[0] = (float)(total / TOTAL);         // LOSS_WEIGHT = 1.0
            g_acc = 0.0;                             // reset for next graph replay
            g_cnt = 0u;
        }
    }
}

extern "C" void kernel_launch(void* const* d_in, const int* in_sizes, int n_in,
                              void* d_out, int out_size) {
    const float* pred    = (const float*)d_in[0];
    const float* sigma   = (const float*)d_in[1];
    const float* teacher = (const float*)d_in[2];
    const float* twgt    = (const float*)d_in[3];
    float* out = (float*)d_out;

    // Opt-in to >48KB dynamic smem (idempotent; not a stream op, capture-safe).
    cudaFuncSetAttribute(loss_kernel,
                         cudaFuncAttributeMaxDynamicSharedMemorySize, SMEM_TOTAL);
    loss_kernel<<<GRID, NTHREADS, SMEM_TOTAL>>>(pred, sigma, teacher, twgt, out);
}

// round 13
// speedup vs baseline: 2.6474x; 2.6474x over previous
#include <cuda_runtime.h>

// Problem constants
#define NN 512
#define KK 17
#define WW 48
#define HH 64
#define NK (NN * KK)                       // 8704
#define HMSZ (HH * WW)                     // 3072 floats
#define TOTAL ((double)NN * KK * HH * WW)  // 26738688

#define GRID 592                           // 4 blocks/SM * 148 SMs, single wave
#define NWARP 8                            // warps per block (256 threads)
#define GWARPS (GRID * NWARP)              // 4736 warps total

__device__ double g_acc;          // zero-init; reset by last block each run
__device__ unsigned int g_cnt;    // ditto

__global__ __launch_bounds__(256, 4) void loss_kernel(
    const float* __restrict__ pred,      // [N,K,2]
    const float* __restrict__ sigma,     // [N,K,2]
    const float* __restrict__ teacher,   // [N,K,H,W]
    const float* __restrict__ twgt,      // [N,K,1]
    float* __restrict__ out)             // [1]
{
    const int tid  = threadIdx.x;
    const int wid  = tid >> 5;
    const int lane = tid & 31;
    const int gw   = blockIdx.x * NWARP + wid;   // global warp id

    // Warp-private tables: [0..47] = ex, [48..111] = ey (row padded to 128)
    __shared__ __align__(16) float tab[NWARP][128];
    float* ex  = tab[wid];
    float* eyp = tab[wid] + 48;

    float acc = 0.0f;

    for (int nk = gw; nk < NK; nk += GWARPS) {
        // ---- Uniform params (same-address LDG -> broadcast) ----
        const float mux = pred[nk * 2 + 0] * (float)WW;
        const float muy = pred[nk * 2 + 1] * (float)HH;
        const float sx  = sigma[nk * 2 + 0];
        const float sy  = sigma[nk * 2 + 1];
        const float twv = twgt[nk];

        const float m = ((mux - 3.0f * sx < (float)WW) &&
                         (muy - 3.0f * sy < (float)HH) &&
                         (mux + 3.0f * sx + 1.0f >= 0.0f) &&
                         (muy + 3.0f * sy + 1.0f >= 0.0f)) ? 1.0f : 0.0f;
        const float tw   = twv * m;
        const float coef = tw * tw;
        const float invx = 1.0f / (sx * sx + 1e-9f);
        const float invy = 1.0f / (sy * sy + 1e-9f);

        // ---- Build warp-private tables (<=4 exps per lane) ----
        __syncwarp();                      // prior consume finished before overwrite
        {
            float d = (float)lane - mux;
            ex[lane] = __expf(-0.5f * d * d * invx);
            if (lane < WW - 32) {
                float d2 = (float)(lane + 32) - mux;
                ex[lane + 32] = __expf(-0.5f * d2 * d2 * invx);
            }
            float dy = (float)lane - muy;
            eyp[lane] = __expf(-0.5f * dy * dy * invy);
            float dy2 = (float)(lane + 32) - muy;
            eyp[lane + 32] = __expf(-0.5f * dy2 * dy2 * invy);
        }
        __syncwarp();                      // tables visible to the warp

        // ---- Stream this warp's heatmap: 24 float4 per lane ----
        const float4* __restrict__ tp  = reinterpret_cast<const float4*>(teacher + (size_t)nk * HMSZ);
        const float4* __restrict__ ex4 = reinterpret_cast<const float4*>(ex);

        float wsum = 0.0f;
#pragma unroll 6
        for (int k = 0; k < 24; k++) {
            const int q = lane + 32 * k;   // quad index 0..767
            const float4 t = tp[q];
            const int h = q / 12;          // 12 quads per row (W=48)
            const int c = q % 12;
            const float4 e = ex4[c];       // LDS.128
            const float  y = eyp[h];       // LDS (broadcasty)

            float d0 = e.x * y - t.x;
            float d1 = e.y * y - t.y;
            float d2 = e.z * y - t.z;
            float d3 = e.w * y - t.w;
            wsum += d0 * d0 + d1 * d1 + d2 * d2 + d3 * d3;
        }
        acc += wsum * coef;
    }

    // ---- Block reduce (single __syncthreads in the kernel) ----
    __shared__ float s_warp[NWARP];
#pragma unroll
    for (int off = 16; off > 0; off >>= 1)
        acc += __shfl_down_sync(0xFFFFFFFFu, acc, off);
    if (lane == 0) s_warp[wid] = acc;
    __syncthreads();

    if (tid < NWARP) {
        float v = s_warp[tid];
#pragma unroll
        for (int off = NWARP / 2; off > 0; off >>= 1)
            v += __shfl_down_sync((1u << NWARP) - 1u, v, off);
        if (tid == 0) {
            atomicAdd(&g_acc, (double)v);
            __threadfence();
            unsigned int ticket = atomicAdd(&g_cnt, 1u);
            if (ticket == GRID - 1) {
                double total = atomicAdd(&g_acc, 0.0);   // coherent read
                out[0] = (float)(total / TOTAL);         // LOSS_WEIGHT = 1.0
                g_acc = 0.0;                             // reset for next replay
                g_cnt = 0u;
            }
        }
    }
}

extern "C" void kernel_launch(void* const* d_in, const int* in_sizes, int n_in,
                              void* d_out, int out_size) {
    const float* pred    = (const float*)d_in[0];
    const float* sigma   = (const float*)d_in[1];
    const float* teacher = (const float*)d_in[2];
    const float* twgt    = (const float*)d_in[3];
    float* out = (float*)d_out;

    loss_kernel<<<GRID, 256>>>(pred, sigma, teacher, twgt, out);
}

// round 14
// speedup vs baseline: 4.1746x; 1.5769x over previous
#include <cuda_runtime.h>

// Problem constants
#define NN 512
#define KK 17
#define WW 48
#define HH 64
#define NK (NN * KK)                       // 8704
#define HMSZ (HH * WW)                     // 3072 floats
#define TOTAL ((double)NN * KK * HH * WW)  // 26738688

#define GRID 592                           // 4 blocks/SM * 148 SMs, single wave
#define NWARP 8                            // warps per block (256 threads)
#define GWARPS (GRID * NWARP)              // 4736 warps total

__device__ double g_acc;          // zero-init; reset by last block each run
__device__ unsigned int g_cnt;    // ditto

__global__ __launch_bounds__(256, 4) void loss_kernel(
    const float* __restrict__ pred,      // [N,K,2]
    const float* __restrict__ sigma,     // [N,K,2]
    const float* __restrict__ teacher,   // [N,K,H,W]
    const float* __restrict__ twgt,      // [N,K,1]
    float* __restrict__ out)             // [1]
{
    const int tid  = threadIdx.x;
    const int wid  = tid >> 5;
    const int lane = tid & 31;
    const int gw   = blockIdx.x * NWARP + wid;   // global warp id

    // Warp-private double-buffered tables: [0..47]=ex, [48..111]=ey
    __shared__ __align__(16) float tab[NWARP][2][128];

    const float2* __restrict__ pred2  = (const float2*)pred;
    const float2* __restrict__ sigma2 = (const float2*)sigma;

    float acc = 0.0f;

    // ---- Prime params for first heatmap ----
    float2 pr, sg;
    float  tv;
    if (gw < NK) {
        pr = pred2[gw];
        sg = sigma2[gw];
        tv = twgt[gw];
    } else {
        pr = make_float2(0.f, 0.f); sg = make_float2(1.f, 1.f); tv = 0.f;
    }

    int b = 0;
    for (int nk = gw; nk < NK; nk += GWARPS) {
        // ---- Prefetch NEXT heatmap's params (land during current stream) ----
        const int nk2 = nk + GWARPS;
        float2 prn, sgn;
        float  tvn;
        if (nk2 < NK) {
            prn = pred2[nk2];
            sgn = sigma2[nk2];
            tvn = twgt[nk2];
        } else {
            prn = make_float2(0.f, 0.f); sgn = make_float2(1.f, 1.f); tvn = 0.f;
        }

        // ---- Tables for current heatmap (params already in registers) ----
        const float mux = pr.x * (float)WW;
        const float muy = pr.y * (float)HH;
        const float sx  = sg.x;
        const float sy  = sg.y;
        const float m = ((mux - 3.0f * sx < (float)WW) &&
                         (muy - 3.0f * sy < (float)HH) &&
                         (mux + 3.0f * sx + 1.0f >= 0.0f) &&
                         (muy + 3.0f * sy + 1.0f >= 0.0f)) ? 1.0f : 0.0f;
        const float tw   = tv * m;
        const float coef = tw * tw;
        const float invx = 1.0f / (sx * sx + 1e-9f);
        const float invy = 1.0f / (sy * sy + 1e-9f);

        float* exb = tab[wid][b];
        float* eyb = tab[wid][b] + 48;
        {
            float d = (float)lane - mux;
            exb[lane] = __expf(-0.5f * d * d * invx);
            if (lane < WW - 32) {
                float d2 = (float)(lane + 32) - mux;
                exb[lane + 32] = __expf(-0.5f * d2 * d2 * invx);
            }
            float dy = (float)lane - muy;
            eyb[lane] = __expf(-0.5f * dy * dy * invy);
            float dy2 = (float)(lane + 32) - muy;
            eyb[lane + 32] = __expf(-0.5f * dy2 * dy2 * invy);
        }
        __syncwarp();   // tables visible; double-buffer bounds cross-iter slip

        // ---- Stream this warp's heatmap: 24 float4 per lane ----
        const float4* __restrict__ tp  = reinterpret_cast<const float4*>(teacher + (size_t)nk * HMSZ);
        const float4* __restrict__ ex4 = reinterpret_cast<const float4*>(exb);

        float wsum = 0.0f;
#pragma unroll 6
        for (int k = 0; k < 24; k++) {
            const int q = lane + 32 * k;   // quad index 0..767
            const float4 t = tp[q];
            const int h = q / 12;          // 12 quads per row (W=48)
            const int c = q % 12;
            const float4 e = ex4[c];       // LDS.128
            const float  y = eyb[h];       // LDS

            float d0 = e.x * y - t.x;
            float d1 = e.y * y - t.y;
            float d2 = e.z * y - t.z;
            float d3 = e.w * y - t.w;
            wsum += d0 * d0 + d1 * d1 + d2 * d2 + d3 * d3;
        }
        acc += wsum * coef;

        // ---- Shift pipeline ----
        pr = prn; sg = sgn; tv = tvn;
        b ^= 1;
    }

    // ---- Block reduce (single __syncthreads in the kernel) ----
    __shared__ float s_warp[NWARP];
#pragma unroll
    for (int off = 16; off > 0; off >>= 1)
        acc += __shfl_down_sync(0xFFFFFFFFu, acc, off);
    if (lane == 0) s_warp[wid] = acc;
    __syncthreads();

    if (tid < NWARP) {
        float v = s_warp[tid];
#pragma unroll
        for (int off = NWARP / 2; off > 0; off >>= 1)
            v += __shfl_down_sync((1u << NWARP) - 1u, v, off);
        if (tid == 0) {
            atomicAdd(&g_acc, (double)v);
            __threadfence();
            unsigned int ticket = atomicAdd(&g_cnt, 1u);
            if (ticket == GRID - 1) {
                double total = atomicAdd(&g_acc, 0.0);   // coherent read
                out[0] = (float)(total / TOTAL);         // LOSS_WEIGHT = 1.0
                g_acc = 0.0;                             // reset for next replay
                g_cnt = 0u;
            }
        }
    }
}

extern "C" void kernel_launch(void* const* d_in, const int* in_sizes, int n_in,
                              void* d_out, int out_size) {
    const float* pred    = (const float*)d_in[0];
    const float* sigma   = (const float*)d_in[1];
    const float* teacher = (const float*)d_in[2];
    const float* twgt    = (const float*)d_in[3];
    float* out = (float*)d_out;

    loss_kernel<<<GRID, 256>>>(pred, sigma, teacher, twgt, out);
}